// round 5
// baseline (speedup 1.0000x reference)
#include <cuda_runtime.h>
#include <cuda_fp16.h>
#include <math.h>
#include <stdint.h>

#define F_IN   4096
#define F_OUT  2048
#define BATCH  2048
#define N_ITER 10
#define SECURE_MIN 1e-5f
#define EPS_NORM   1e-20f

// static power-of-2 operand scales (exact; cancelled analytically)
#define S_W   65536.0f   // Wn, WnT
#define S_H   4096.0f    // ht
#define S_R   256.0f     // ratio
#define S_REC 4096.0f    // recon (half storage)
#define S_X   4096.0f    // xn (half storage)
#define ESC1 (1.0f / (S_H * S_W))   // acc1 -> recon_true
#define ESC2 (1.0f / (S_R * S_W))   // acc2 -> update_true

// ---------------- GEMM tiling ----------------
#define BM 128
#define BN 256
#define BK 64                        // 64 halves = 128 B per row
#define STAGES 4
#define A_TILE_BYTES (BM * 128)      // 16 KB
#define B_TILE_BYTES (BN * 128)      // 32 KB
#define STAGE_BYTES (A_TILE_BYTES + B_TILE_BYTES)
#define SMEM_TOTAL (STAGES * STAGE_BYTES)   // 192 KB

// ---------------- scratch ----------------
__device__ __align__(1024) __half g_Wn_h  [(size_t)F_OUT * F_IN];
__device__ __align__(1024) __half g_WnT_h [(size_t)F_IN  * F_OUT];
__device__ __align__(1024) __half g_rat_h [(size_t)BATCH * F_IN];
__device__ __align__(1024) __half g_ht_h  [(size_t)BATCH * F_OUT];
__device__ __align__(1024) __half g_xn_h  [(size_t)BATCH * F_IN];
__device__ __align__(1024) __half g_rec_h [(size_t)BATCH * F_IN];

// ---------------- PTX helpers ----------------
__device__ __forceinline__ uint32_t smem_u32(const void* p) {
    uint32_t a;
    asm("{ .reg .u64 t; cvta.to.shared.u64 t, %1; cvt.u32.u64 %0, t; }"
        : "=r"(a) : "l"(p));
    return a;
}
__device__ __forceinline__ void cp_async16(uint32_t dst, const void* src) {
    asm volatile("cp.async.cg.shared.global [%0], [%1], 16;"
                 :: "r"(dst), "l"(src) : "memory");
}
__device__ __forceinline__ void cp_commit() {
    asm volatile("cp.async.commit_group;" ::: "memory");
}
template <int N>
__device__ __forceinline__ void cp_wait() {
    asm volatile("cp.async.wait_group %0;" :: "n"(N) : "memory");
}
__device__ __forceinline__ void ldm_x4(uint32_t& r0, uint32_t& r1,
                                       uint32_t& r2, uint32_t& r3, uint32_t a) {
    asm volatile("ldmatrix.sync.aligned.m8n8.x4.shared.b16 {%0,%1,%2,%3}, [%4];"
                 : "=r"(r0), "=r"(r1), "=r"(r2), "=r"(r3) : "r"(a));
}
__device__ __forceinline__ void mma_f16(float* d, const uint32_t* a,
                                        const uint32_t* b) {
    asm volatile(
        "mma.sync.aligned.m16n8k16.row.col.f32.f16.f16.f32 "
        "{%0,%1,%2,%3}, {%4,%5,%6,%7}, {%8,%9}, {%0,%1,%2,%3};"
        : "+f"(d[0]), "+f"(d[1]), "+f"(d[2]), "+f"(d[3])
        : "r"(a[0]), "r"(a[1]), "r"(a[2]), "r"(a[3]), "r"(b[0]), "r"(b[1]));
}

// ---------------- fp16 mma.sync GEMM, 64x64 warp tiles ----------------
// EPI=1: Ch = half(max(acc*ESC1, 1e-5) * S_REC)       (recon, half out)
// EPI=2: Cf = max(Cf_old * acc*ESC2, 1e-5)            (h update, fp32 in/out)
template <int EPI>
__global__ void __launch_bounds__(256, 1)
gemm_f16(const __half* __restrict__ A, const __half* __restrict__ B,
         __half* __restrict__ Ch, float* __restrict__ Cf, int K, int Nglob) {
    extern __shared__ char smem[];
    const uint32_t sb = smem_u32(smem);

    const int tid  = threadIdx.x;
    const int warp = tid >> 5;
    const int lane = tid & 31;
    const int m0 = blockIdx.y * BM;
    const int n0 = blockIdx.x * BN;
    const int wm = (warp >> 2) << 6;   // 0,64
    const int wn = (warp & 3) << 6;    // 0,64,128,192

    // cp.async mapping: A 1024 chunks (4/thr), B 2048 chunks (8/thr)
    const int crow = tid >> 3;
    const int cch  = tid & 7;

    // ldmatrix lane addressing
    const int rowA = wm + (lane & 15);
    const int selA = lane >> 4;
    const int rowB0 = wn + (lane & 7) + ((lane & 16) ? 8 : 0);
    const int selB = (lane >> 3) & 1;

    float acc[4][8][4];
#pragma unroll
    for (int i = 0; i < 4; i++)
#pragma unroll
        for (int j = 0; j < 8; j++)
#pragma unroll
            for (int k = 0; k < 4; k++) acc[i][j][k] = 0.0f;

    const int nkt = K / BK;

    auto load_stage = [&](int kt, int st) {
        const uint32_t sA = sb + st * STAGE_BYTES;
        const uint32_t sB = sA + A_TILE_BYTES;
        const __half* gA = A + (size_t)m0 * K + kt * BK;
        const __half* gB = B + (size_t)n0 * K + kt * BK;
#pragma unroll
        for (int q = 0; q < 4; q++) {
            const int r = crow + q * 32;
            const uint32_t soff = r * 128 + ((cch ^ (r & 7)) << 4);
            cp_async16(sA + soff, gA + (size_t)r * K + cch * 8);
        }
#pragma unroll
        for (int q = 0; q < 8; q++) {
            const int r = crow + q * 32;
            const uint32_t soff = r * 128 + ((cch ^ (r & 7)) << 4);
            cp_async16(sB + soff, gB + (size_t)r * K + cch * 8);
        }
        cp_commit();
    };

    load_stage(0, 0);
    load_stage(1, 1);
    load_stage(2, 2);

    for (int kt = 0; kt < nkt; kt++) {
        cp_wait<2>();
        __syncthreads();
        if (kt + 3 < nkt) load_stage(kt + 3, (kt + 3) % STAGES);
        else cp_commit();

        const uint32_t sA = sb + (kt % STAGES) * STAGE_BYTES;
        const uint32_t sB = sA + A_TILE_BYTES;
#pragma unroll
        for (int ks = 0; ks < BK / 16; ks++) {
            uint32_t a[4][4], b[4][4];
#pragma unroll
            for (int mi = 0; mi < 4; mi++) {
                const int r = rowA + mi * 16;
                const uint32_t ad = sA + r * 128 +
                                    (((ks * 2 + selA) ^ (r & 7)) << 4);
                ldm_x4(a[mi][0], a[mi][1], a[mi][2], a[mi][3], ad);
            }
#pragma unroll
            for (int g = 0; g < 4; g++) {
                const int r = rowB0 + g * 16;
                const uint32_t bd = sB + r * 128 +
                                    (((ks * 2 + selB) ^ (r & 7)) << 4);
                ldm_x4(b[g][0], b[g][1], b[g][2], b[g][3], bd);
            }
#pragma unroll
            for (int mi = 0; mi < 4; mi++)
#pragma unroll
                for (int g = 0; g < 4; g++) {
                    mma_f16(acc[mi][2 * g + 0], a[mi], &b[g][0]);
                    mma_f16(acc[mi][2 * g + 1], a[mi], &b[g][2]);
                }
        }
        __syncthreads();
    }

    const int erow = m0 + wm + (lane >> 2);
    const int ecol = n0 + wn + (lane & 3) * 2;
#pragma unroll
    for (int mi = 0; mi < 4; mi++) {
#pragma unroll
        for (int ni = 0; ni < 8; ni++) {
#pragma unroll
            for (int hf = 0; hf < 2; hf++) {
                const int r = erow + mi * 16 + hf * 8;
                const int c = ecol + ni * 8;
                float vx = acc[mi][ni][2 * hf + 0];
                float vy = acc[mi][ni][2 * hf + 1];
                if (EPI == 1) {
                    // recon half: max(acc*ESC1,1e-5)*S_REC
                    vx = fmaxf(vx * (ESC1 * S_REC), SECURE_MIN * S_REC);
                    vy = fmaxf(vy * (ESC1 * S_REC), SECURE_MIN * S_REC);
                    *(half2*)(Ch + (size_t)r * Nglob + c) =
                        __floats2half2_rn(vx, vy);
                } else {
                    float* p = Cf + (size_t)r * Nglob + c;
                    float2 h = *(const float2*)p;
                    float2 v;
                    v.x = fmaxf(h.x * (vx * ESC2), SECURE_MIN);
                    v.y = fmaxf(h.y * (vy * ESC2), SECURE_MIN);
                    *(float2*)p = v;
                }
            }
        }
    }
}

// ---------------- elementwise ----------------
__device__ __forceinline__ float block_reduce_sum(float v) {
    __shared__ float ws[8];
    const int lane = threadIdx.x & 31;
    const int w    = threadIdx.x >> 5;
#pragma unroll
    for (int o = 16; o > 0; o >>= 1) v += __shfl_xor_sync(0xffffffffu, v, o);
    if (lane == 0) ws[w] = v;
    __syncthreads();
    if (w == 0) {
        v = (lane < 8) ? ws[lane] : 0.0f;
#pragma unroll
        for (int o = 4; o > 0; o >>= 1) v += __shfl_xor_sync(0xffffffffu, v, o);
        if (lane == 0) ws[0] = v;
    }
    __syncthreads();
    return ws[0];
}

__device__ __forceinline__ void store_h4(__half* dst, size_t i4, float4 v,
                                         float scale) {
    half2* p = (half2*)(dst + i4 * 4);
    p[0] = __floats2half2_rn(v.x * scale, v.y * scale);
    p[1] = __floats2half2_rn(v.z * scale, v.w * scale);
}

// MODE 0: dst_h = half(S_X * l1norm(src))                 (xn)
// MODE 1: dst_h = half(S_W * l1norm(max(src,1e-5)))       (Wn prep)
// MODE 2: dst_f = l1norm(src); dst_h = half(S_H * same)   (h + ht)
template <int MODE>
__global__ void rownorm_kernel(const float* __restrict__ src,
                               float* __restrict__ dst_f,
                               __half* __restrict__ dst_h, int cols) {
    const size_t base = (size_t)blockIdx.x * cols;
    const float4* s4 = (const float4*)(src + base);
    const int n4 = cols >> 2;
    float sum = 0.0f;
    for (int i = threadIdx.x; i < n4; i += blockDim.x) {
        float4 v = s4[i];
        if (MODE == 1) {
            v.x = fmaxf(v.x, SECURE_MIN); v.y = fmaxf(v.y, SECURE_MIN);
            v.z = fmaxf(v.z, SECURE_MIN); v.w = fmaxf(v.w, SECURE_MIN);
        }
        sum += fabsf(v.x) + fabsf(v.y) + fabsf(v.z) + fabsf(v.w);
    }
    const float tot = block_reduce_sum(sum);
    const float inv = 1.0f / fmaxf(tot, EPS_NORM);
    for (int i = threadIdx.x; i < n4; i += blockDim.x) {
        float4 v = s4[i];
        if (MODE == 1) {
            v.x = fmaxf(v.x, SECURE_MIN); v.y = fmaxf(v.y, SECURE_MIN);
            v.z = fmaxf(v.z, SECURE_MIN); v.w = fmaxf(v.w, SECURE_MIN);
        }
        v.x *= inv; v.y *= inv; v.z *= inv; v.w *= inv;
        if (MODE == 2) ((float4*)(dst_f + base))[i] = v;
        if (MODE == 0) store_h4(dst_h + base, i, v, S_X);
        if (MODE == 1) store_h4(dst_h + base, i, v, S_W);
        if (MODE == 2) store_h4(dst_h + base, i, v, S_H);
    }
}

// all-half ratio: rec_h = S_REC*recon_true, xn_h = S_X*xn_true.
// rat = half( S_R * xn_true * max(rowsum(recon_true),eps) / recon_true )
//     = half( xn_h * factor / rec_h ),  factor = max(sum_h/S_REC,eps)*S_REC*S_R/S_X
__global__ void ratio_kernel(const __half* __restrict__ rec_h,
                             const __half* __restrict__ xn_h,
                             __half* __restrict__ rat_h, int cols) {
    const size_t base = (size_t)blockIdx.x * cols;
    const half2* r2 = (const half2*)(rec_h + base);
    const half2* x2 = (const half2*)(xn_h + base);
    half2*       o2 = (half2*)(rat_h + base);
    const int n2 = cols >> 1;
    float sum = 0.0f;
    for (int i = threadIdx.x; i < n2; i += blockDim.x) {
        float2 v = __half22float2(r2[i]);
        sum += v.x + v.y;
    }
    float s = block_reduce_sum(sum);                 // = S_REC * true_sum
    const float factor = fmaxf(s / S_REC, EPS_NORM) * (S_REC * S_R / S_X);
    for (int i = threadIdx.x; i < n2; i += blockDim.x) {
        float2 v = __half22float2(r2[i]);
        float2 x = __half22float2(x2[i]);
        o2[i] = __floats2half2_rn(x.x * factor / v.x, x.y * factor / v.y);
    }
}

__global__ void transpose_h_kernel(const __half* __restrict__ in,
                                   __half* __restrict__ out, int rows, int cols) {
    __shared__ __half tile[32][33];
    const int c  = blockIdx.x * 32 + threadIdx.x;
    const int r0 = blockIdx.y * 32;
#pragma unroll
    for (int i = threadIdx.y; i < 32; i += 8)
        tile[i][threadIdx.x] = in[(size_t)(r0 + i) * cols + c];
    __syncthreads();
    const int rO = r0 + threadIdx.x;
    const int c0 = blockIdx.x * 32;
#pragma unroll
    for (int i = threadIdx.y; i < 32; i += 8)
        out[(size_t)(c0 + i) * rows + rO] = tile[threadIdx.x][i];
}

__global__ void fill_kernel(float* __restrict__ a, __half* __restrict__ b,
                            float val, float val_h, int n) {
    const int i = blockIdx.x * blockDim.x + threadIdx.x;
    if (i < n) { a[i] = val; b[i] = __float2half_rn(val_h); }
}

// ---------------- host ----------------
extern "C" void kernel_launch(void* const* d_in, const int* in_sizes, int n_in,
                              void* d_out, int out_size) {
    const float* x = (const float*)d_in[0];  // (BATCH, F_IN)
    const float* W = (const float*)d_in[1];  // (F_OUT, F_IN)
    float* h = (float*)d_out;                // (BATCH, F_OUT)

    __half *Wn, *WnT, *rat, *ht, *xn, *rec;
    cudaGetSymbolAddress((void**)&Wn,  g_Wn_h);
    cudaGetSymbolAddress((void**)&WnT, g_WnT_h);
    cudaGetSymbolAddress((void**)&rat, g_rat_h);
    cudaGetSymbolAddress((void**)&ht,  g_ht_h);
    cudaGetSymbolAddress((void**)&xn,  g_xn_h);
    cudaGetSymbolAddress((void**)&rec, g_rec_h);

    cudaFuncSetAttribute(gemm_f16<1>, cudaFuncAttributeMaxDynamicSharedMemorySize, SMEM_TOTAL);
    cudaFuncSetAttribute(gemm_f16<2>, cudaFuncAttributeMaxDynamicSharedMemorySize, SMEM_TOTAL);

    // prep
    rownorm_kernel<1><<<F_OUT, 256>>>(W, nullptr, Wn, F_IN);
    rownorm_kernel<0><<<BATCH, 256>>>(x, nullptr, xn, F_IN);
    transpose_h_kernel<<<dim3(F_IN / 32, F_OUT / 32), dim3(32, 8)>>>(Wn, WnT, F_OUT, F_IN);
    fill_kernel<<<(BATCH * F_OUT + 255) / 256, 256>>>(
        h, ht, 1.0f / (float)F_OUT, S_H / (float)F_OUT, BATCH * F_OUT);

    for (int it = 0; it < N_ITER; ++it) {
        // rec[B, F_IN] = half(clip(ht @ Wn)) : A=ht (K=F_OUT), Brows=WnT
        gemm_f16<1><<<dim3(F_IN / BN, BATCH / BM), 256, SMEM_TOTAL>>>(
            ht, WnT, rec, nullptr, F_OUT, F_IN);
        ratio_kernel<<<BATCH, 256>>>(rec, xn, rat, F_IN);
        // h[B, F_OUT] = max(h * (rat @ WnT), min) : A=rat (K=F_IN), Brows=Wn
        gemm_f16<2><<<dim3(F_OUT / BN, BATCH / BM), 256, SMEM_TOTAL>>>(
            rat, Wn, nullptr, h, F_IN, F_OUT);
        rownorm_kernel<2><<<BATCH, 256>>>(h, h, ht, F_OUT);
    }
}

// round 6
// speedup vs baseline: 1.1114x; 1.1114x over previous
#include <cuda_runtime.h>
#include <cuda_fp16.h>
#include <math.h>
#include <stdint.h>

#define F_IN   4096
#define F_OUT  2048
#define BATCH  2048
#define N_ITER 10
#define SECURE_MIN 1e-5f
#define EPS_NORM   1e-20f

// static power-of-2 operand scales (exact; cancelled analytically)
#define S_W   65536.0f   // Wn, WnT
#define S_H   4096.0f    // ht
#define S_R   256.0f     // ratio
#define S_REC 4096.0f    // recon half storage
#define S_X   4096.0f    // xn half storage
#define ESC1 (1.0f / (S_H * S_W))
#define ESC2 (1.0f / (S_R * S_W))

// ---------------- GEMM tiling (round-4 proven config) ----------------
#define BM 128
#define BN 128
#define BK 64                        // 64 halves = 128 B per row
#define STAGES 3
#define TILE_BYTES (BM * 128)        // 16 KB each
#define STAGE_BYTES (2 * TILE_BYTES)
#define SMEM_TOTAL (STAGES * STAGE_BYTES)  // 96 KB -> 2 CTA/SM

// ---------------- scratch ----------------
__device__ __align__(1024) __half g_Wn_h  [(size_t)F_OUT * F_IN];
__device__ __align__(1024) __half g_WnT_h [(size_t)F_IN  * F_OUT];
__device__ __align__(1024) __half g_rat_h [(size_t)BATCH * F_IN];
__device__ __align__(1024) __half g_ht_h  [(size_t)BATCH * F_OUT];
__device__ __align__(1024) __half g_xn_h  [(size_t)BATCH * F_IN];
__device__ __align__(1024) __half g_rec_h [(size_t)BATCH * F_IN];
__device__ float g_rec0[F_IN];      // first-iter broadcast recon (true units)
__device__ float g_s0;              // sum of rec0

// ---------------- PTX helpers ----------------
__device__ __forceinline__ uint32_t smem_u32(const void* p) {
    uint32_t a;
    asm("{ .reg .u64 t; cvta.to.shared.u64 t, %1; cvt.u32.u64 %0, t; }"
        : "=r"(a) : "l"(p));
    return a;
}
__device__ __forceinline__ void cp_async16(uint32_t dst, const void* src) {
    asm volatile("cp.async.cg.shared.global [%0], [%1], 16;"
                 :: "r"(dst), "l"(src) : "memory");
}
__device__ __forceinline__ void cp_commit() {
    asm volatile("cp.async.commit_group;" ::: "memory");
}
template <int N>
__device__ __forceinline__ void cp_wait() {
    asm volatile("cp.async.wait_group %0;" :: "n"(N) : "memory");
}
__device__ __forceinline__ void ldm_x4(uint32_t& r0, uint32_t& r1,
                                       uint32_t& r2, uint32_t& r3, uint32_t a) {
    asm volatile("ldmatrix.sync.aligned.m8n8.x4.shared.b16 {%0,%1,%2,%3}, [%4];"
                 : "=r"(r0), "=r"(r1), "=r"(r2), "=r"(r3) : "r"(a));
}
__device__ __forceinline__ void mma_f16(float* d, const uint32_t* a,
                                        const uint32_t* b) {
    asm volatile(
        "mma.sync.aligned.m16n8k16.row.col.f32.f16.f16.f32 "
        "{%0,%1,%2,%3}, {%4,%5,%6,%7}, {%8,%9}, {%0,%1,%2,%3};"
        : "+f"(d[0]), "+f"(d[1]), "+f"(d[2]), "+f"(d[3])
        : "r"(a[0]), "r"(a[1]), "r"(a[2]), "r"(a[3]), "r"(b[0]), "r"(b[1]));
}

// ---------------- fp16 mma.sync GEMM (32x64 warptiles, 2 CTA/SM) -------
// EPI=1: Ch = half(max(acc*ESC1, 1e-5) * S_REC)           (recon half)
// EPI=2: Cf = max(Cf_old * acc*ESC2, 1e-5)                (h update)
// EPI=3: Cf = max((1/F_OUT) * acc*ESC2, 1e-5)             (first h update)
template <int EPI>
__global__ void __launch_bounds__(256, 2)
gemm_f16(const __half* __restrict__ A, const __half* __restrict__ B,
         __half* __restrict__ Ch, float* __restrict__ Cf, int K, int Nglob) {
    extern __shared__ char smem[];
    const uint32_t sb = smem_u32(smem);

    const int tid  = threadIdx.x;
    const int warp = tid >> 5;
    const int lane = tid & 31;
    const int m0 = blockIdx.y * BM;
    const int n0 = blockIdx.x * BN;
    const int wm = (warp >> 1) << 5;   // 0,32,64,96
    const int wn = (warp & 1) << 6;    // 0,64

    const int crow = tid >> 3;
    const int cch  = tid & 7;

    const int rowA = wm + (lane & 15);
    const int selA = lane >> 4;
    const int rowB0 = wn + (lane & 7) + ((lane & 16) ? 8 : 0);
    const int selB = (lane >> 3) & 1;

    float acc[2][8][4];
#pragma unroll
    for (int i = 0; i < 2; i++)
#pragma unroll
        for (int j = 0; j < 8; j++)
#pragma unroll
            for (int k = 0; k < 4; k++) acc[i][j][k] = 0.0f;

    const int nkt = K / BK;

    auto load_stage = [&](int kt, int st) {
        const uint32_t sA = sb + st * STAGE_BYTES;
        const uint32_t sB = sA + TILE_BYTES;
        const __half* gA = A + (size_t)m0 * K + kt * BK;
        const __half* gB = B + (size_t)n0 * K + kt * BK;
#pragma unroll
        for (int q = 0; q < 4; q++) {
            const int r = crow + q * 32;
            const uint32_t soff = r * 128 + ((cch ^ (r & 7)) << 4);
            cp_async16(sA + soff, gA + (size_t)r * K + cch * 8);
            cp_async16(sB + soff, gB + (size_t)r * K + cch * 8);
        }
        cp_commit();
    };

    load_stage(0, 0);
    if (nkt > 1) load_stage(1, 1); else cp_commit();

    for (int kt = 0; kt < nkt; kt++) {
        cp_wait<1>();
        __syncthreads();
        if (kt + 2 < nkt) load_stage(kt + 2, (kt + 2) % STAGES);
        else cp_commit();

        const uint32_t sA = sb + (kt % STAGES) * STAGE_BYTES;
        const uint32_t sB = sA + TILE_BYTES;
#pragma unroll
        for (int ks = 0; ks < BK / 16; ks++) {
            uint32_t a[2][4], b[4][4];
#pragma unroll
            for (int mi = 0; mi < 2; mi++) {
                const int r = rowA + mi * 16;
                const uint32_t ad = sA + r * 128 +
                                    (((ks * 2 + selA) ^ (r & 7)) << 4);
                ldm_x4(a[mi][0], a[mi][1], a[mi][2], a[mi][3], ad);
            }
#pragma unroll
            for (int g = 0; g < 4; g++) {
                const int r = rowB0 + g * 16;
                const uint32_t bd = sB + r * 128 +
                                    (((ks * 2 + selB) ^ (r & 7)) << 4);
                ldm_x4(b[g][0], b[g][1], b[g][2], b[g][3], bd);
            }
#pragma unroll
            for (int mi = 0; mi < 2; mi++)
#pragma unroll
                for (int g = 0; g < 4; g++) {
                    mma_f16(acc[mi][2 * g + 0], a[mi], &b[g][0]);
                    mma_f16(acc[mi][2 * g + 1], a[mi], &b[g][2]);
                }
        }
        __syncthreads();
    }

    const int erow = m0 + wm + (lane >> 2);
    const int ecol = n0 + wn + (lane & 3) * 2;
#pragma unroll
    for (int mi = 0; mi < 2; mi++) {
#pragma unroll
        for (int ni = 0; ni < 8; ni++) {
#pragma unroll
            for (int hf = 0; hf < 2; hf++) {
                const int r = erow + mi * 16 + hf * 8;
                const int c = ecol + ni * 8;
                float vx = acc[mi][ni][2 * hf + 0];
                float vy = acc[mi][ni][2 * hf + 1];
                if (EPI == 1) {
                    vx = fmaxf(vx * (ESC1 * S_REC), SECURE_MIN * S_REC);
                    vy = fmaxf(vy * (ESC1 * S_REC), SECURE_MIN * S_REC);
                    *(half2*)(Ch + (size_t)r * Nglob + c) =
                        __floats2half2_rn(vx, vy);
                } else if (EPI == 2) {
                    float* p = Cf + (size_t)r * Nglob + c;
                    float2 h = *(const float2*)p;
                    float2 v;
                    v.x = fmaxf(h.x * (vx * ESC2), SECURE_MIN);
                    v.y = fmaxf(h.y * (vy * ESC2), SECURE_MIN);
                    *(float2*)p = v;
                } else { // EPI == 3: h0 = 1/F_OUT constant
                    float* p = Cf + (size_t)r * Nglob + c;
                    const float h0e = (1.0f / (float)F_OUT) * ESC2;
                    float2 v;
                    v.x = fmaxf(vx * h0e, SECURE_MIN);
                    v.y = fmaxf(vy * h0e, SECURE_MIN);
                    *(float2*)p = v;
                }
            }
        }
    }
}

// ---------------- elementwise ----------------
__device__ __forceinline__ float block_reduce_sum(float v) {
    __shared__ float ws[8];
    const int lane = threadIdx.x & 31;
    const int w    = threadIdx.x >> 5;
#pragma unroll
    for (int o = 16; o > 0; o >>= 1) v += __shfl_xor_sync(0xffffffffu, v, o);
    if (lane == 0) ws[w] = v;
    __syncthreads();
    if (w == 0) {
        v = (lane < 8) ? ws[lane] : 0.0f;
#pragma unroll
        for (int o = 4; o > 0; o >>= 1) v += __shfl_xor_sync(0xffffffffu, v, o);
        if (lane == 0) ws[0] = v;
    }
    __syncthreads();
    return ws[0];
}

__device__ __forceinline__ void store_h4(__half* dst, size_t i4, float4 v,
                                         float scale) {
    half2* p = (half2*)(dst + i4 * 4);
    p[0] = __floats2half2_rn(v.x * scale, v.y * scale);
    p[1] = __floats2half2_rn(v.z * scale, v.w * scale);
}

// MODE 0: dst_h = half(S_X * l1norm(src))                 (xn)
// MODE 1: dst_h = half(S_W * l1norm(max(src,1e-5)))       (Wn)
// MODE 2: dst_f = l1norm(src); dst_h = half(S_H * same)   (h + ht)
template <int MODE>
__global__ void rownorm_kernel(const float* __restrict__ src,
                               float* __restrict__ dst_f,
                               __half* __restrict__ dst_h, int cols) {
    const size_t base = (size_t)blockIdx.x * cols;
    const float4* s4 = (const float4*)(src + base);
    const int n4 = cols >> 2;
    float sum = 0.0f;
    for (int i = threadIdx.x; i < n4; i += blockDim.x) {
        float4 v = s4[i];
        if (MODE == 1) {
            v.x = fmaxf(v.x, SECURE_MIN); v.y = fmaxf(v.y, SECURE_MIN);
            v.z = fmaxf(v.z, SECURE_MIN); v.w = fmaxf(v.w, SECURE_MIN);
        }
        sum += fabsf(v.x) + fabsf(v.y) + fabsf(v.z) + fabsf(v.w);
    }
    const float tot = block_reduce_sum(sum);
    const float inv = 1.0f / fmaxf(tot, EPS_NORM);
    for (int i = threadIdx.x; i < n4; i += blockDim.x) {
        float4 v = s4[i];
        if (MODE == 1) {
            v.x = fmaxf(v.x, SECURE_MIN); v.y = fmaxf(v.y, SECURE_MIN);
            v.z = fmaxf(v.z, SECURE_MIN); v.w = fmaxf(v.w, SECURE_MIN);
        }
        v.x *= inv; v.y *= inv; v.z *= inv; v.w *= inv;
        if (MODE == 2) ((float4*)(dst_f + base))[i] = v;
        if (MODE == 0) store_h4(dst_h + base, i, v, S_X);
        if (MODE == 1) store_h4(dst_h + base, i, v, S_W);
        if (MODE == 2) store_h4(dst_h + base, i, v, S_H);
    }
}

// ratio (iters >= 2): all-half
__global__ void ratio_kernel(const __half* __restrict__ rec_h,
                             const __half* __restrict__ xn_h,
                             __half* __restrict__ rat_h, int cols) {
    const size_t base = (size_t)blockIdx.x * cols;
    const half2* r2 = (const half2*)(rec_h + base);
    const half2* x2 = (const half2*)(xn_h + base);
    half2*       o2 = (half2*)(rat_h + base);
    const int n2 = cols >> 1;
    float sum = 0.0f;
    for (int i = threadIdx.x; i < n2; i += blockDim.x) {
        float2 v = __half22float2(r2[i]);
        sum += v.x + v.y;
    }
    float s = block_reduce_sum(sum);                 // = S_REC * true_sum
    const float factor = fmaxf(s / S_REC, EPS_NORM) * (S_REC * S_R / S_X);
    for (int i = threadIdx.x; i < n2; i += blockDim.x) {
        float2 v = __half22float2(r2[i]);
        float2 x = __half22float2(x2[i]);
        o2[i] = __floats2half2_rn(x.x * factor / v.x, x.y * factor / v.y);
    }
}

// first-iter: rec0[i] = max((1/F_OUT) * sum_f Wn_true[f][i], 1e-5)
__global__ void colsum_kernel(const __half* __restrict__ Wn_h,
                              float* __restrict__ rec0) {
    const int col = blockIdx.x * blockDim.x + threadIdx.x;  // 0..F_IN-1
    float s = 0.0f;
    for (int f = 0; f < F_OUT; f++)
        s += __half2float(Wn_h[(size_t)f * F_IN + col]);
    rec0[col] = fmaxf(s / (S_W * (float)F_OUT), SECURE_MIN);
}

// single-block sum of rec0 -> g_s0
__global__ void sum_rec0_kernel(const float* __restrict__ rec0,
                                float* __restrict__ s0) {
    float v = 0.0f;
    for (int i = threadIdx.x; i < F_IN; i += blockDim.x) v += rec0[i];
    float t = block_reduce_sum(v);
    if (threadIdx.x == 0) *s0 = fmaxf(t, EPS_NORM);
}

// first-iter ratio broadcast: rat_h[b,i] = half((S_R/S_X) * s0 / rec0[i] * xn_h[b,i])
__global__ void ratio0_kernel(const float* __restrict__ rec0,
                              const float* __restrict__ s0,
                              const __half* __restrict__ xn_h,
                              __half* __restrict__ rat_h) {
    const float sf = (*s0) * (S_R / S_X);
    const size_t base = (size_t)blockIdx.x * F_IN;
    const half2* x2 = (const half2*)(xn_h + base);
    half2*       o2 = (half2*)(rat_h + base);
    const float2* r2 = (const float2*)rec0;
    for (int i = threadIdx.x; i < F_IN / 2; i += blockDim.x) {
        float2 x = __half22float2(x2[i]);
        float2 r = r2[i];
        o2[i] = __floats2half2_rn(x.x * sf / r.x, x.y * sf / r.y);
    }
}

__global__ void transpose_h_kernel(const __half* __restrict__ in,
                                   __half* __restrict__ out, int rows, int cols) {
    __shared__ __half tile[32][33];
    const int c  = blockIdx.x * 32 + threadIdx.x;
    const int r0 = blockIdx.y * 32;
#pragma unroll
    for (int i = threadIdx.y; i < 32; i += 8)
        tile[i][threadIdx.x] = in[(size_t)(r0 + i) * cols + c];
    __syncthreads();
    const int rO = r0 + threadIdx.x;
    const int c0 = blockIdx.x * 32;
#pragma unroll
    for (int i = threadIdx.y; i < 32; i += 8)
        out[(size_t)(c0 + i) * rows + rO] = tile[threadIdx.x][i];
}

// ---------------- host ----------------
extern "C" void kernel_launch(void* const* d_in, const int* in_sizes, int n_in,
                              void* d_out, int out_size) {
    const float* x = (const float*)d_in[0];  // (BATCH, F_IN)
    const float* W = (const float*)d_in[1];  // (F_OUT, F_IN)
    float* h = (float*)d_out;                // (BATCH, F_OUT)

    __half *Wn, *WnT, *rat, *ht, *xn, *rec;
    float *rec0, *s0;
    cudaGetSymbolAddress((void**)&Wn,   g_Wn_h);
    cudaGetSymbolAddress((void**)&WnT,  g_WnT_h);
    cudaGetSymbolAddress((void**)&rat,  g_rat_h);
    cudaGetSymbolAddress((void**)&ht,   g_ht_h);
    cudaGetSymbolAddress((void**)&xn,   g_xn_h);
    cudaGetSymbolAddress((void**)&rec,  g_rec_h);
    cudaGetSymbolAddress((void**)&rec0, g_rec0);
    cudaGetSymbolAddress((void**)&s0,   g_s0);

    cudaFuncSetAttribute(gemm_f16<1>, cudaFuncAttributeMaxDynamicSharedMemorySize, SMEM_TOTAL);
    cudaFuncSetAttribute(gemm_f16<2>, cudaFuncAttributeMaxDynamicSharedMemorySize, SMEM_TOTAL);
    cudaFuncSetAttribute(gemm_f16<3>, cudaFuncAttributeMaxDynamicSharedMemorySize, SMEM_TOTAL);

    // prep
    rownorm_kernel<1><<<F_OUT, 256>>>(W, nullptr, Wn, F_IN);
    rownorm_kernel<0><<<BATCH, 256>>>(x, nullptr, xn, F_IN);
    transpose_h_kernel<<<dim3(F_IN / 32, F_OUT / 32), dim3(32, 8)>>>(Wn, WnT, F_OUT, F_IN);

    // ---- iteration 1 (h0 uniform => recon is a broadcast vector) ----
    colsum_kernel<<<F_IN / 256, 256>>>(Wn, rec0);
    sum_rec0_kernel<<<1, 1024>>>(rec0, s0);
    ratio0_kernel<<<BATCH, 256>>>(rec0, s0, xn, rat);
    gemm_f16<3><<<dim3(F_OUT / BN, BATCH / BM), 256, SMEM_TOTAL>>>(
        rat, Wn, nullptr, h, F_IN, F_OUT);
    rownorm_kernel<2><<<BATCH, 256>>>(h, h, ht, F_OUT);

    // ---- iterations 2..N ----
    for (int it = 1; it < N_ITER; ++it) {
        gemm_f16<1><<<dim3(F_IN / BN, BATCH / BM), 256, SMEM_TOTAL>>>(
            ht, WnT, rec, nullptr, F_OUT, F_IN);
        ratio_kernel<<<BATCH, 256>>>(rec, xn, rat, F_IN);
        gemm_f16<2><<<dim3(F_OUT / BN, BATCH / BM), 256, SMEM_TOTAL>>>(
            rat, Wn, nullptr, h, F_IN, F_OUT);
        rownorm_kernel<2><<<BATCH, 256>>>(h, h, ht, F_OUT);
    }
}

// round 7
// speedup vs baseline: 1.1781x; 1.0599x over previous
#include <cuda_runtime.h>
#include <cuda_fp16.h>
#include <math.h>
#include <stdint.h>

#define F_IN   4096
#define F_OUT  2048
#define BATCH  2048
#define N_ITER 10
#define SECURE_MIN 1e-5f
#define EPS_NORM   1e-20f

// static power-of-2 operand scales (exact; cancelled analytically)
#define S_W   65536.0f   // Wn, WnT
#define S_H   4096.0f    // ht
#define S_R   256.0f     // ratio
#define S_REC 4096.0f    // recon half storage
#define S_X   4096.0f    // xn half storage
#define ESC1 (1.0f / (S_H * S_W))
#define ESC2 (1.0f / (S_R * S_W))

// ---------------- GEMM tiling (proven config) ----------------
#define BM 128
#define BN 128
#define BK 64                        // 64 halves = 128 B per row
#define STAGES 3
#define TILE_BYTES (BM * 128)        // 16 KB each
#define STAGE_BYTES (2 * TILE_BYTES)
#define SMEM_TOTAL (STAGES * STAGE_BYTES)  // 96 KB -> 2 CTA/SM

// ---------------- scratch ----------------
__device__ __align__(1024) __half g_Wn_h  [(size_t)F_OUT * F_IN];
__device__ __align__(1024) __half g_WnT_h [(size_t)F_IN  * F_OUT];
__device__ __align__(1024) __half g_rat_h [(size_t)BATCH * F_IN];
__device__ __align__(1024) __half g_ht_h  [(size_t)BATCH * F_OUT];
__device__ __align__(1024) __half g_xn_h  [(size_t)BATCH * F_IN];
__device__ __align__(1024) __half g_rec_h [(size_t)BATCH * F_IN];
__device__ float g_rec0[F_IN];      // first-iter broadcast recon (true units)
__device__ float g_s0;              // sum of clipped rec0
__device__ float g_rowsum[BATCH];   // per-row sum of clipped recon (true units)

// ---------------- PTX helpers ----------------
__device__ __forceinline__ uint32_t smem_u32(const void* p) {
    uint32_t a;
    asm("{ .reg .u64 t; cvta.to.shared.u64 t, %1; cvt.u32.u64 %0, t; }"
        : "=r"(a) : "l"(p));
    return a;
}
__device__ __forceinline__ void cp_async16(uint32_t dst, const void* src) {
    asm volatile("cp.async.cg.shared.global [%0], [%1], 16;"
                 :: "r"(dst), "l"(src) : "memory");
}
__device__ __forceinline__ void cp_commit() {
    asm volatile("cp.async.commit_group;" ::: "memory");
}
template <int N>
__device__ __forceinline__ void cp_wait() {
    asm volatile("cp.async.wait_group %0;" :: "n"(N) : "memory");
}
__device__ __forceinline__ void ldm_x4(uint32_t& r0, uint32_t& r1,
                                       uint32_t& r2, uint32_t& r3, uint32_t a) {
    asm volatile("ldmatrix.sync.aligned.m8n8.x4.shared.b16 {%0,%1,%2,%3}, [%4];"
                 : "=r"(r0), "=r"(r1), "=r"(r2), "=r"(r3) : "r"(a));
}
__device__ __forceinline__ void mma_f16(float* d, const uint32_t* a,
                                        const uint32_t* b) {
    asm volatile(
        "mma.sync.aligned.m16n8k16.row.col.f32.f16.f16.f32 "
        "{%0,%1,%2,%3}, {%4,%5,%6,%7}, {%8,%9}, {%0,%1,%2,%3};"
        : "+f"(d[0]), "+f"(d[1]), "+f"(d[2]), "+f"(d[3])
        : "r"(a[0]), "r"(a[1]), "r"(a[2]), "r"(a[3]), "r"(b[0]), "r"(b[1]));
}

// ---------------- fp16 mma.sync GEMM (32x64 warptiles, 2 CTA/SM) -------
// EPI=1: Ch = half(max(acc*ESC1,1e-5)*S_REC); rowsum[r] += clipped (fp32)
// EPI=2: Cf = max(Cf_old * acc*ESC2, 1e-5)
// EPI=3: Cf = max((1/F_OUT) * acc*ESC2, 1e-5)
template <int EPI>
__global__ void __launch_bounds__(256, 2)
gemm_f16(const __half* __restrict__ A, const __half* __restrict__ B,
         __half* __restrict__ Ch, float* __restrict__ Cf,
         float* __restrict__ rowsum, int K, int Nglob) {
    extern __shared__ char smem[];
    const uint32_t sb = smem_u32(smem);

    const int tid  = threadIdx.x;
    const int warp = tid >> 5;
    const int lane = tid & 31;
    const int m0 = blockIdx.y * BM;
    const int n0 = blockIdx.x * BN;
    const int wm = (warp >> 1) << 5;   // 0,32,64,96
    const int wn = (warp & 1) << 6;    // 0,64

    const int crow = tid >> 3;
    const int cch  = tid & 7;

    const int rowA = wm + (lane & 15);
    const int selA = lane >> 4;
    const int rowB0 = wn + (lane & 7) + ((lane & 16) ? 8 : 0);
    const int selB = (lane >> 3) & 1;

    float acc[2][8][4];
#pragma unroll
    for (int i = 0; i < 2; i++)
#pragma unroll
        for (int j = 0; j < 8; j++)
#pragma unroll
            for (int k = 0; k < 4; k++) acc[i][j][k] = 0.0f;

    const int nkt = K / BK;

    auto load_stage = [&](int kt, int st) {
        const uint32_t sA = sb + st * STAGE_BYTES;
        const uint32_t sB = sA + TILE_BYTES;
        const __half* gA = A + (size_t)m0 * K + kt * BK;
        const __half* gB = B + (size_t)n0 * K + kt * BK;
#pragma unroll
        for (int q = 0; q < 4; q++) {
            const int r = crow + q * 32;
            const uint32_t soff = r * 128 + ((cch ^ (r & 7)) << 4);
            cp_async16(sA + soff, gA + (size_t)r * K + cch * 8);
            cp_async16(sB + soff, gB + (size_t)r * K + cch * 8);
        }
        cp_commit();
    };

    load_stage(0, 0);
    if (nkt > 1) load_stage(1, 1); else cp_commit();

    for (int kt = 0; kt < nkt; kt++) {
        cp_wait<1>();
        __syncthreads();
        if (kt + 2 < nkt) load_stage(kt + 2, (kt + 2) % STAGES);
        else cp_commit();

        const uint32_t sA = sb + (kt % STAGES) * STAGE_BYTES;
        const uint32_t sB = sA + TILE_BYTES;
#pragma unroll
        for (int ks = 0; ks < BK / 16; ks++) {
            uint32_t a[2][4], b[4][4];
#pragma unroll
            for (int mi = 0; mi < 2; mi++) {
                const int r = rowA + mi * 16;
                const uint32_t ad = sA + r * 128 +
                                    (((ks * 2 + selA) ^ (r & 7)) << 4);
                ldm_x4(a[mi][0], a[mi][1], a[mi][2], a[mi][3], ad);
            }
#pragma unroll
            for (int g = 0; g < 4; g++) {
                const int r = rowB0 + g * 16;
                const uint32_t bd = sB + r * 128 +
                                    (((ks * 2 + selB) ^ (r & 7)) << 4);
                ldm_x4(b[g][0], b[g][1], b[g][2], b[g][3], bd);
            }
#pragma unroll
            for (int mi = 0; mi < 2; mi++)
#pragma unroll
                for (int g = 0; g < 4; g++) {
                    mma_f16(acc[mi][2 * g + 0], a[mi], &b[g][0]);
                    mma_f16(acc[mi][2 * g + 1], a[mi], &b[g][2]);
                }
        }
        __syncthreads();
    }

    const int erow = m0 + wm + (lane >> 2);
    const int ecol = n0 + wn + (lane & 3) * 2;
#pragma unroll
    for (int mi = 0; mi < 2; mi++) {
#pragma unroll
        for (int hf = 0; hf < 2; hf++) {
            const int r = erow + mi * 16 + hf * 8;
            float rs = 0.0f;
#pragma unroll
            for (int ni = 0; ni < 8; ni++) {
                const int c = ecol + ni * 8;
                float vx = acc[mi][ni][2 * hf + 0];
                float vy = acc[mi][ni][2 * hf + 1];
                if (EPI == 1) {
                    const float ux = fmaxf(vx * ESC1, SECURE_MIN);
                    const float uy = fmaxf(vy * ESC1, SECURE_MIN);
                    rs += ux + uy;
                    *(half2*)(Ch + (size_t)r * Nglob + c) =
                        __floats2half2_rn(ux * S_REC, uy * S_REC);
                } else if (EPI == 2) {
                    float* p = Cf + (size_t)r * Nglob + c;
                    float2 h = *(const float2*)p;
                    float2 v;
                    v.x = fmaxf(h.x * (vx * ESC2), SECURE_MIN);
                    v.y = fmaxf(h.y * (vy * ESC2), SECURE_MIN);
                    *(float2*)p = v;
                } else { // EPI == 3: h0 = 1/F_OUT constant
                    float* p = Cf + (size_t)r * Nglob + c;
                    const float h0e = (1.0f / (float)F_OUT) * ESC2;
                    float2 v;
                    v.x = fmaxf(vx * h0e, SECURE_MIN);
                    v.y = fmaxf(vy * h0e, SECURE_MIN);
                    *(float2*)p = v;
                }
            }
            if (EPI == 1) {
                // reduce across the 4 lanes sharing this row, one RED per group
                rs += __shfl_xor_sync(0xffffffffu, rs, 1);
                rs += __shfl_xor_sync(0xffffffffu, rs, 2);
                if ((lane & 3) == 0) atomicAdd(&rowsum[r], rs);
            }
        }
    }
}

// ---------------- elementwise ----------------
__device__ __forceinline__ float block_reduce_sum(float v) {
    __shared__ float ws[8];
    const int lane = threadIdx.x & 31;
    const int w    = threadIdx.x >> 5;
#pragma unroll
    for (int o = 16; o > 0; o >>= 1) v += __shfl_xor_sync(0xffffffffu, v, o);
    if (lane == 0) ws[w] = v;
    __syncthreads();
    if (w == 0) {
        v = (lane < 8) ? ws[lane] : 0.0f;
#pragma unroll
        for (int o = 4; o > 0; o >>= 1) v += __shfl_xor_sync(0xffffffffu, v, o);
        if (lane == 0) ws[0] = v;
    }
    __syncthreads();
    return ws[0];
}

__device__ __forceinline__ void store_h4(__half* dst, size_t i4, float4 v,
                                         float scale) {
    half2* p = (half2*)(dst + i4 * 4);
    p[0] = __floats2half2_rn(v.x * scale, v.y * scale);
    p[1] = __floats2half2_rn(v.z * scale, v.w * scale);
}

// register-cached row L1 normalize (ITEMS = cols/4/256 float4 per thread)
// MODE 0: dst_h = half(S_X * l1norm(src))                 (xn)
// MODE 1: dst_h = half(S_W * l1norm(max(src,1e-5)))       (Wn)
// MODE 2: dst_f = l1norm(src); dst_h = half(S_H * same);
//         thread0 zeroes rowsum[blockIdx.x]               (h + ht)
template <int MODE, int ITEMS>
__global__ void __launch_bounds__(256)
rownorm_kernel(const float* __restrict__ src, float* __restrict__ dst_f,
               __half* __restrict__ dst_h, float* __restrict__ rowsum,
               int cols) {
    const size_t base = (size_t)blockIdx.x * cols;
    const float4* s4 = (const float4*)(src + base);
    if (MODE == 2 && threadIdx.x == 0) rowsum[blockIdx.x] = 0.0f;

    float4 v[ITEMS];
    float sum = 0.0f;
#pragma unroll
    for (int q = 0; q < ITEMS; q++) {
        v[q] = s4[threadIdx.x + q * 256];
        if (MODE == 1) {
            v[q].x = fmaxf(v[q].x, SECURE_MIN); v[q].y = fmaxf(v[q].y, SECURE_MIN);
            v[q].z = fmaxf(v[q].z, SECURE_MIN); v[q].w = fmaxf(v[q].w, SECURE_MIN);
        }
        sum += fabsf(v[q].x) + fabsf(v[q].y) + fabsf(v[q].z) + fabsf(v[q].w);
    }
    const float tot = block_reduce_sum(sum);
    const float inv = 1.0f / fmaxf(tot, EPS_NORM);
#pragma unroll
    for (int q = 0; q < ITEMS; q++) {
        const int i = threadIdx.x + q * 256;
        float4 u = v[q];
        u.x *= inv; u.y *= inv; u.z *= inv; u.w *= inv;
        if (MODE == 2) ((float4*)(dst_f + base))[i] = u;
        if (MODE == 0) store_h4(dst_h + base, i, u, S_X);
        if (MODE == 1) store_h4(dst_h + base, i, u, S_W);
        if (MODE == 2) store_h4(dst_h + base, i, u, S_H);
    }
}

// single-pass ratio using fused rowsum from GEMM1 epilogue
__global__ void __launch_bounds__(256)
ratio_kernel(const __half* __restrict__ rec_h, const __half* __restrict__ xn_h,
             const float* __restrict__ rowsum, __half* __restrict__ rat_h,
             int cols) {
    const size_t base = (size_t)blockIdx.x * cols;
    const half2* r2 = (const half2*)(rec_h + base);
    const half2* x2 = (const half2*)(xn_h + base);
    half2*       o2 = (half2*)(rat_h + base);
    const float factor = fmaxf(rowsum[blockIdx.x], EPS_NORM) *
                         (S_R * S_REC / S_X);
    const int n2 = cols >> 1;
    for (int i = threadIdx.x; i < n2; i += 256) {
        float2 v = __half22float2(r2[i]);
        float2 x = __half22float2(x2[i]);
        o2[i] = __floats2half2_rn(x.x * factor / v.x, x.y * factor / v.y);
    }
}

// first-iter: rec0[i] = max(colsum_true(Wn col i), 1e-5) via WnT row sums;
// also accumulates s0 = sum(rec0). One warp per WnT row.
__global__ void __launch_bounds__(256)
colsumT_kernel(const __half* __restrict__ WnT_h, float* __restrict__ rec0,
               float* __restrict__ s0) {
    const int row = blockIdx.x * 8 + (threadIdx.x >> 5);   // 0..F_IN-1
    const int lane = threadIdx.x & 31;
    const half2* p2 = (const half2*)(WnT_h + (size_t)row * F_OUT);
    float s = 0.0f;
    for (int i = lane; i < F_OUT / 2; i += 32) {
        float2 v = __half22float2(p2[i]);
        s += v.x + v.y;
    }
#pragma unroll
    for (int o = 16; o > 0; o >>= 1) s += __shfl_xor_sync(0xffffffffu, s, o);
    if (lane == 0) {
        const float r = fmaxf(s / (S_W * (float)F_OUT), SECURE_MIN);
        rec0[row] = r;
        atomicAdd(s0, r);
    }
}

// first-iter ratio: rat = half((S_R/S_X) * s0 / rec0[i] * xn_h)
__global__ void __launch_bounds__(256)
ratio0_kernel(const float* __restrict__ rec0, const float* __restrict__ s0,
              const __half* __restrict__ xn_h, __half* __restrict__ rat_h) {
    const float sf = fmaxf(*s0, EPS_NORM) * (S_R / S_X);
    const size_t base = (size_t)blockIdx.x * F_IN;
    const half2* x2 = (const half2*)(xn_h + base);
    half2*       o2 = (half2*)(rat_h + base);
    const float2* r2 = (const float2*)rec0;
    for (int i = threadIdx.x; i < F_IN / 2; i += 256) {
        float2 x = __half22float2(x2[i]);
        float2 r = r2[i];
        o2[i] = __floats2half2_rn(x.x * sf / r.x, x.y * sf / r.y);
    }
}

__global__ void transpose_h_kernel(const __half* __restrict__ in,
                                   __half* __restrict__ out, int rows, int cols,
                                   float* __restrict__ s0_zero) {
    if (blockIdx.x == 0 && blockIdx.y == 0 && threadIdx.x == 0 && threadIdx.y == 0)
        *s0_zero = 0.0f;
    __shared__ __half tile[32][33];
    const int c  = blockIdx.x * 32 + threadIdx.x;
    const int r0 = blockIdx.y * 32;
#pragma unroll
    for (int i = threadIdx.y; i < 32; i += 8)
        tile[i][threadIdx.x] = in[(size_t)(r0 + i) * cols + c];
    __syncthreads();
    const int rO = r0 + threadIdx.x;
    const int c0 = blockIdx.x * 32;
#pragma unroll
    for (int i = threadIdx.y; i < 32; i += 8)
        out[(size_t)(c0 + i) * rows + rO] = tile[threadIdx.x][i];
}

// ---------------- host ----------------
extern "C" void kernel_launch(void* const* d_in, const int* in_sizes, int n_in,
                              void* d_out, int out_size) {
    const float* x = (const float*)d_in[0];  // (BATCH, F_IN)
    const float* W = (const float*)d_in[1];  // (F_OUT, F_IN)
    float* h = (float*)d_out;                // (BATCH, F_OUT)

    __half *Wn, *WnT, *rat, *ht, *xn, *rec;
    float *rec0, *s0, *rowsum;
    cudaGetSymbolAddress((void**)&Wn,     g_Wn_h);
    cudaGetSymbolAddress((void**)&WnT,    g_WnT_h);
    cudaGetSymbolAddress((void**)&rat,    g_rat_h);
    cudaGetSymbolAddress((void**)&ht,     g_ht_h);
    cudaGetSymbolAddress((void**)&xn,     g_xn_h);
    cudaGetSymbolAddress((void**)&rec,    g_rec_h);
    cudaGetSymbolAddress((void**)&rec0,   g_rec0);
    cudaGetSymbolAddress((void**)&s0,     g_s0);
    cudaGetSymbolAddress((void**)&rowsum, g_rowsum);

    cudaFuncSetAttribute(gemm_f16<1>, cudaFuncAttributeMaxDynamicSharedMemorySize, SMEM_TOTAL);
    cudaFuncSetAttribute(gemm_f16<2>, cudaFuncAttributeMaxDynamicSharedMemorySize, SMEM_TOTAL);
    cudaFuncSetAttribute(gemm_f16<3>, cudaFuncAttributeMaxDynamicSharedMemorySize, SMEM_TOTAL);

    // prep (transpose also zeroes s0)
    rownorm_kernel<1, 4><<<F_OUT, 256>>>(W, nullptr, Wn, nullptr, F_IN);
    rownorm_kernel<0, 4><<<BATCH, 256>>>(x, nullptr, xn, nullptr, F_IN);
    transpose_h_kernel<<<dim3(F_IN / 32, F_OUT / 32), dim3(32, 8)>>>(
        Wn, WnT, F_OUT, F_IN, s0);

    // ---- iteration 1 (h0 uniform => recon is a broadcast vector) ----
    colsumT_kernel<<<F_IN / 8, 256>>>(WnT, rec0, s0);
    ratio0_kernel<<<BATCH, 256>>>(rec0, s0, xn, rat);
    gemm_f16<3><<<dim3(F_OUT / BN, BATCH / BM), 256, SMEM_TOTAL>>>(
        rat, Wn, nullptr, h, nullptr, F_IN, F_OUT);
    rownorm_kernel<2, 2><<<BATCH, 256>>>(h, h, ht, rowsum, F_OUT);

    // ---- iterations 2..N ----
    for (int it = 1; it < N_ITER; ++it) {
        gemm_f16<1><<<dim3(F_IN / BN, BATCH / BM), 256, SMEM_TOTAL>>>(
            ht, WnT, rec, nullptr, rowsum, F_OUT, F_IN);
        ratio_kernel<<<BATCH, 256>>>(rec, xn, rowsum, rat, F_IN);
        gemm_f16<2><<<dim3(F_OUT / BN, BATCH / BM), 256, SMEM_TOTAL>>>(
            rat, Wn, nullptr, h, nullptr, F_IN, F_OUT);
        rownorm_kernel<2, 2><<<BATCH, 256>>>(h, h, ht, rowsum, F_OUT);
    }
}